// round 11
// baseline (speedup 1.0000x reference)
#include <cuda_runtime.h>
#include <cuda_bf16.h>
#include <cstdint>

// Problem constants
#define NB 8          // batch
#define NL 512        // sequence length
#define NS 64         // spans per batch
#define NR 512        // NB*NS total span rows
#define D1 1024       // D
#define D2 2048       // 2*D

// ---------------------------------------------------------------------------
// Device scratch (no allocations allowed)
// ---------------------------------------------------------------------------
__device__ float g_gs [NR * D1];
__device__ float g_ge [NR * D1];
__device__ float g_t1s[NR * D2];
__device__ float g_t1e[NR * D2];
__device__ float g_cat[NR * D2];
__device__ float g_ent[NR * D2];
__device__ float g_hi [NR * D2];   // ent @ Wr1[:2048] + br1   (bias folded)
__device__ float g_hj [NR * D2];   // ent @ Wr1[2048:]
__device__ __nv_bfloat16 g_w2hi[D1 * D2];   // Wr2^T hi part  [n][k]
__device__ __nv_bfloat16 g_w2lo[D1 * D2];   // Wr2^T lo part  [n][k]

// ---------------------------------------------------------------------------
// PTX helpers (portable: sm_80-level features only)
// ---------------------------------------------------------------------------
static __device__ __forceinline__ uint32_t smem_u32(const void* p) {
    uint32_t a;
    asm("{ .reg .u64 t; cvta.to.shared.u64 t, %1; cvt.u32.u64 %0, t; }"
        : "=r"(a) : "l"(p));
    return a;
}

static __device__ __forceinline__ void cp16(uint32_t dst, const void* src) {
    asm volatile("cp.async.cg.shared.global [%0], [%1], 16;"
                 :: "r"(dst), "l"(src));
}
#define CP_COMMIT() asm volatile("cp.async.commit_group;" ::: "memory")
#define CP_WAIT(n)  asm volatile("cp.async.wait_group %0;" :: "n"(n) : "memory")

static __device__ __forceinline__ void ldsm4(uint32_t r[4], uint32_t addr) {
    asm volatile("ldmatrix.sync.aligned.m8n8.x4.shared.b16 {%0,%1,%2,%3}, [%4];"
                 : "=r"(r[0]), "=r"(r[1]), "=r"(r[2]), "=r"(r[3]) : "r"(addr));
}

static __device__ __forceinline__ void mma16816(float c[4], const uint32_t a[4],
                                                uint32_t b0, uint32_t b1) {
    asm volatile(
        "mma.sync.aligned.m16n8k16.row.col.f32.bf16.bf16.f32 "
        "{%0,%1,%2,%3}, {%4,%5,%6,%7}, {%8,%9}, {%0,%1,%2,%3};"
        : "+f"(c[0]), "+f"(c[1]), "+f"(c[2]), "+f"(c[3])
        : "r"(a[0]), "r"(a[1]), "r"(a[2]), "r"(a[3]), "r"(b0), "r"(b1));
}

static __device__ __forceinline__ uint32_t pack_bf16(__nv_bfloat16 a, __nv_bfloat16 b) {
    __nv_bfloat162 t = __halves2bfloat162(a, b);
    return *(uint32_t*)&t;
}

// ---------------------------------------------------------------------------
// Gather
// ---------------------------------------------------------------------------
__global__ void gather_kernel(const float* __restrict__ h,
                              const int* __restrict__ span)
{
    int bn = blockIdx.x;
    int b  = bn >> 6;
    int si = span[2 * bn + 0];
    int ei = span[2 * bn + 1];
    const float4* ps = (const float4*)(h + ((size_t)b * NL + (size_t)si) * D1);
    const float4* pe = (const float4*)(h + ((size_t)b * NL + (size_t)ei) * D1);
    float4* ds = (float4*)(g_gs + (size_t)bn * D1);
    float4* de = (float4*)(g_ge + (size_t)bn * D1);
    for (int t = threadIdx.x; t < D1 / 4; t += blockDim.x) {
        ds[t] = ps[t];
        de[t] = pe[t];
    }
}

// ---------------------------------------------------------------------------
// Prep: Wr2 (2048 x 1024, row-major) -> transposed bf16 hi/lo (1024 x 2048)
// ---------------------------------------------------------------------------
__global__ void prep_wr2_kernel(const float* __restrict__ W)
{
    __shared__ float tile[32][33];
    int n0 = blockIdx.x * 32;
    int k0 = blockIdx.y * 32;
    int tx = threadIdx.x, ty = threadIdx.y;
    for (int i = ty; i < 32; i += 8)
        tile[i][tx] = W[(size_t)(k0 + i) * D1 + n0 + tx];
    __syncthreads();
    for (int i = ty; i < 32; i += 8) {
        float v = tile[tx][i];               // = Wr2[k0+tx][n0+i]
        __nv_bfloat16 hv = __float2bfloat16_rn(v);
        float lof = v - __bfloat162float(hv);
        size_t o = (size_t)(n0 + i) * D2 + k0 + tx;
        g_w2hi[o] = hv;
        g_w2lo[o] = __float2bfloat16_rn(lof);
    }
}

// ---------------------------------------------------------------------------
// Generic fp32 SGEMM (z-batched dual), 128x128 tile, double-buffered cp.async
//   C[M,N] = act(A[M,K] @ W[K,N] + bias)
// ---------------------------------------------------------------------------
#define BM 128
#define BN 128
#define BK 8
#define TM 8
#define TN 8

template<bool RELU>
__global__ __launch_bounds__(256)
void gemm_dual_kernel(const float* __restrict__ A0, const float* __restrict__ A1,
                      const float* __restrict__ W0, const float* __restrict__ W1,
                      const float* __restrict__ bias0, const float* __restrict__ bias1,
                      float* __restrict__ C0, float* __restrict__ C1,
                      int N, int K, int ldc)
{
    const float* A    = blockIdx.z ? A1 : A0;
    const float* W    = blockIdx.z ? W1 : W0;
    const float* bias = blockIdx.z ? bias1 : bias0;
    float*       C    = blockIdx.z ? C1 : C0;

    __shared__ float As[2][BK][BM];   // 8 KB
    __shared__ float Bs[2][BK][BN];   // 8 KB

    const int tid = threadIdx.x;
    const int tx  = tid & 15;
    const int ty  = tid >> 4;
    const int rowBase = blockIdx.y * BM;
    const int colBase = blockIdx.x * BN;

    const int l   = tid * 4;
    const int a_r = l >> 3;       // 0..127
    const int a_k = l & 7;        // 0 or 4
    const int b_k = l >> 7;       // 0..7
    const int b_c = l & 127;      // multiple of 4

    float acc[TM][TN];
#pragma unroll
    for (int i = 0; i < TM; i++)
#pragma unroll
        for (int j = 0; j < TN; j++) acc[i][j] = 0.f;

    const float* Aptr = A + (size_t)(rowBase + a_r) * K + a_k;
    const float* Wptr = W + (size_t)b_k * N + colBase + b_c;

    // ---- prologue: stage 0 ----
    {
        float4 av = *(const float4*)(Aptr);
        As[0][a_k + 0][a_r] = av.x;
        As[0][a_k + 1][a_r] = av.y;
        As[0][a_k + 2][a_r] = av.z;
        As[0][a_k + 3][a_r] = av.w;
        cp16(smem_u32(&Bs[0][b_k][b_c]), Wptr);
        CP_COMMIT();
    }

    const int NCK = K / BK;
    for (int c = 0; c < NCK; c++) {
        CP_WAIT(0);
        __syncthreads();          // stage (c&1) ready; stage (c+1)&1 readers done

        const bool more = (c + 1 < NCK);
        float4 an;
        if (more) {
            an = *(const float4*)(Aptr + (size_t)(c + 1) * BK);
            cp16(smem_u32(&Bs[(c + 1) & 1][b_k][b_c]),
                 Wptr + (size_t)(c + 1) * BK * N);
            CP_COMMIT();
        }

        const int buf = c & 1;
#pragma unroll
        for (int kk = 0; kk < BK; kk++) {
            float4 a0 = *(const float4*)&As[buf][kk][ty * TM];
            float4 a1 = *(const float4*)&As[buf][kk][ty * TM + 4];
            float4 b0 = *(const float4*)&Bs[buf][kk][tx * TN];
            float4 b1 = *(const float4*)&Bs[buf][kk][tx * TN + 4];
            float a[TM] = {a0.x, a0.y, a0.z, a0.w, a1.x, a1.y, a1.z, a1.w};
            float bb[TN] = {b0.x, b0.y, b0.z, b0.w, b1.x, b1.y, b1.z, b1.w};
#pragma unroll
            for (int i = 0; i < TM; i++)
#pragma unroll
                for (int j = 0; j < TN; j++)
                    acc[i][j] = fmaf(a[i], bb[j], acc[i][j]);
        }

        if (more) {
            const int nb = (c + 1) & 1;
            As[nb][a_k + 0][a_r] = an.x;
            As[nb][a_k + 1][a_r] = an.y;
            As[nb][a_k + 2][a_r] = an.z;
            As[nb][a_k + 3][a_r] = an.w;
        }
    }

    float bj[TN];
#pragma unroll
    for (int j = 0; j < TN; j++)
        bj[j] = bias ? bias[colBase + tx * TN + j] : 0.f;

#pragma unroll
    for (int i = 0; i < TM; i++) {
        int r = rowBase + ty * TM + i;
        float* cp = C + (size_t)r * ldc + colBase + tx * TN;
#pragma unroll
        for (int j = 0; j < TN; j++) {
            float v = acc[i][j] + bj[j];
            if (RELU) v = fmaxf(v, 0.f);
            cp[j] = v;
        }
    }
}

// ---------------------------------------------------------------------------
// Final GEMM on HMMA (mma.sync bf16, 3-term split, fp32 accum), 2-stage pipe
//   out[m,n] = relu(hi'[b,i,:] + hj[b,j,:]) @ Wr2 + br2     (br1 folded in hi')
//   m = ((b*64+i)*64+j), M=32768, K=2048, N=1024
// ---------------------------------------------------------------------------
#define KC   32
#define NC   (D2 / KC)        // 64 chunks
#define RSTR 80               // bytes per SMEM row (40 bf16, padded)
#define AHO  0
#define ALO_ 10240
#define BHO  20480
#define BLO_ 30720
#define STG  40960            // bytes per stage
#define FINAL_SMEM (2 * STG)  // 81920

__global__ __launch_bounds__(256)
void final_mma_kernel(const float* __restrict__ br2, float* __restrict__ out)
{
    extern __shared__ char smem[];
    const uint32_t sb = smem_u32(smem);
    const int tid  = threadIdx.x;
    const int lane = tid & 31;
    const int wid  = tid >> 5;
    const int wm   = wid >> 2;     // 0..1
    const int wn   = wid & 3;      // 0..3
    const int colBase = blockIdx.x * 128;
    const int rowBase = blockIdx.y * 128;

    const int fr = tid >> 1;
    const int fk = (tid & 1) << 4;
    const int m  = rowBase + fr;
    const int bI = m >> 12, iI = (m >> 6) & 63, jI = m & 63;
    const float* hiRow = g_hi + (size_t)((bI << 6) + iI) * D2;
    const float* hjRow = g_hj + (size_t)((bI << 6) + jI) * D2;
    const __nv_bfloat16* bhRow = g_w2hi + (size_t)(colBase + fr) * D2;
    const __nv_bfloat16* blRow = g_w2lo + (size_t)(colBase + fr) * D2;
    const uint32_t fillOff = (uint32_t)(fr * RSTR + fk * 2);

    float acc[4][4][4];
#pragma unroll
    for (int a = 0; a < 4; a++)
#pragma unroll
        for (int b = 0; b < 4; b++)
#pragma unroll
            for (int c = 0; c < 4; c++) acc[a][b][c] = 0.f;

    auto fill_stage = [&](int c) {
        const int st = (c & 1) * STG;
        const int k0 = c * KC;
        {
            uint32_t d = sb + BHO + st + fillOff;
            cp16(d,      bhRow + k0 + fk);
            cp16(d + 16, bhRow + k0 + fk + 8);
            d = sb + BLO_ + st + fillOff;
            cp16(d,      blRow + k0 + fk);
            cp16(d + 16, blRow + k0 + fk + 8);
        }
        const float4* xp = (const float4*)(hiRow + k0 + fk);
        const float4* yp = (const float4*)(hjRow + k0 + fk);
        uint32_t ah[8], al[8];
#pragma unroll
        for (int q = 0; q < 4; q++) {
            float4 x = xp[q], y = yp[q];
            float v0 = fmaxf(x.x + y.x, 0.f);
            float v1 = fmaxf(x.y + y.y, 0.f);
            float v2 = fmaxf(x.z + y.z, 0.f);
            float v3 = fmaxf(x.w + y.w, 0.f);
            __nv_bfloat16 h0 = __float2bfloat16_rn(v0);
            __nv_bfloat16 h1 = __float2bfloat16_rn(v1);
            __nv_bfloat16 h2 = __float2bfloat16_rn(v2);
            __nv_bfloat16 h3 = __float2bfloat16_rn(v3);
            ah[2 * q + 0] = pack_bf16(h0, h1);
            ah[2 * q + 1] = pack_bf16(h2, h3);
            al[2 * q + 0] = pack_bf16(__float2bfloat16_rn(v0 - __bfloat162float(h0)),
                                      __float2bfloat16_rn(v1 - __bfloat162float(h1)));
            al[2 * q + 1] = pack_bf16(__float2bfloat16_rn(v2 - __bfloat162float(h2)),
                                      __float2bfloat16_rn(v3 - __bfloat162float(h3)));
        }
        char* da = smem + AHO + st + fillOff;
        *(uint4*)(da)      = make_uint4(ah[0], ah[1], ah[2], ah[3]);
        *(uint4*)(da + 16) = make_uint4(ah[4], ah[5], ah[6], ah[7]);
        char* dl = smem + ALO_ + st + fillOff;
        *(uint4*)(dl)      = make_uint4(al[0], al[1], al[2], al[3]);
        *(uint4*)(dl + 16) = make_uint4(al[4], al[5], al[6], al[7]);
    };

    const uint32_t aOff = (uint32_t)((wm * 64 + (lane & 15)) * RSTR + ((lane >> 4) * 8) * 2);
    const uint32_t bOff = (uint32_t)((wn * 32 + (lane & 7) + ((lane >> 4) & 1) * 8) * RSTR
                                     + (((lane >> 3) & 1) * 8) * 2);

    // ---- prologue ----
    fill_stage(0);
    CP_COMMIT();

    for (int c = 0; c < NC; c++) {
        if (c + 1 < NC) {
            fill_stage(c + 1);
            CP_COMMIT();
            CP_WAIT(1);
        } else {
            CP_WAIT(0);
        }
        __syncthreads();   // stage c fully visible

        const int st = (c & 1) * STG;
        const uint32_t aH = sb + AHO + st + aOff;
        const uint32_t aL = sb + ALO_ + st + aOff;
        const uint32_t bH = sb + BHO + st + bOff;
        const uint32_t bL = sb + BLO_ + st + bOff;

#pragma unroll
        for (int ks = 0; ks < KC; ks += 16) {
            uint32_t ah[4][4], al4[4][4], bh[2][4], bl[2][4];
#pragma unroll
            for (int mt = 0; mt < 4; mt++) {
                ldsm4(ah[mt],  aH + mt * (16 * RSTR) + ks * 2);
                ldsm4(al4[mt], aL + mt * (16 * RSTR) + ks * 2);
            }
#pragma unroll
            for (int np = 0; np < 2; np++) {
                ldsm4(bh[np], bH + np * (16 * RSTR) + ks * 2);
                ldsm4(bl[np], bL + np * (16 * RSTR) + ks * 2);
            }
#pragma unroll
            for (int mt = 0; mt < 4; mt++) {
#pragma unroll
                for (int nt = 0; nt < 4; nt++) {
                    const int np = nt >> 1, h = (nt & 1) * 2;
                    mma16816(acc[mt][nt], ah[mt],  bh[np][h], bh[np][h + 1]);
                    mma16816(acc[mt][nt], ah[mt],  bl[np][h], bl[np][h + 1]);
                    mma16816(acc[mt][nt], al4[mt], bh[np][h], bh[np][h + 1]);
                }
            }
        }
        __syncthreads();   // readers done before refill of this stage
    }

    // ---- epilogue: acc -> out (+br2) ----
#pragma unroll
    for (int mt = 0; mt < 4; mt++) {
        const int r0 = rowBase + wm * 64 + mt * 16 + (lane >> 2);
#pragma unroll
        for (int nt = 0; nt < 4; nt++) {
            const int col = colBase + wn * 32 + nt * 8 + (lane & 3) * 2;
            const float b0 = br2[col], b1 = br2[col + 1];
            float2 v01 = make_float2(acc[mt][nt][0] + b0, acc[mt][nt][1] + b1);
            float2 v23 = make_float2(acc[mt][nt][2] + b0, acc[mt][nt][3] + b1);
            *(float2*)(out + (size_t)r0 * D1 + col)       = v01;
            *(float2*)(out + (size_t)(r0 + 8) * D1 + col) = v23;
        }
    }
}

// ---------------------------------------------------------------------------
// Launcher
// ---------------------------------------------------------------------------
extern "C" void kernel_launch(void* const* d_in, const int* in_sizes, int n_in,
                              void* d_out, int out_size)
{
    const float* h    = (const float*)d_in[0];
    const int*   span = (const int*)d_in[1];
    const float* Ws1 = (const float*)d_in[2];
    const float* bs1 = (const float*)d_in[3];
    const float* Ws2 = (const float*)d_in[4];
    const float* bs2 = (const float*)d_in[5];
    const float* We1 = (const float*)d_in[6];
    const float* be1 = (const float*)d_in[7];
    const float* We2 = (const float*)d_in[8];
    const float* be2 = (const float*)d_in[9];
    const float* Wo  = (const float*)d_in[10];
    const float* bo  = (const float*)d_in[11];
    const float* Wr1 = (const float*)d_in[12];
    const float* br1 = (const float*)d_in[13];
    const float* Wr2 = (const float*)d_in[14];
    const float* br2 = (const float*)d_in[15];
    float* out = (float*)d_out;

    float *gs, *ge, *t1s, *t1e, *cat, *ent, *hi, *hj;
    cudaGetSymbolAddress((void**)&gs,  g_gs);
    cudaGetSymbolAddress((void**)&ge,  g_ge);
    cudaGetSymbolAddress((void**)&t1s, g_t1s);
    cudaGetSymbolAddress((void**)&t1e, g_t1e);
    cudaGetSymbolAddress((void**)&cat, g_cat);
    cudaGetSymbolAddress((void**)&ent, g_ent);
    cudaGetSymbolAddress((void**)&hi,  g_hi);
    cudaGetSymbolAddress((void**)&hj,  g_hj);

    cudaFuncSetAttribute(final_mma_kernel,
                         cudaFuncAttributeMaxDynamicSharedMemorySize, FINAL_SMEM);

    // 0) prep: transpose + bf16-split Wr2 (independent)
    prep_wr2_kernel<<<dim3(D1 / 32, D2 / 32), dim3(32, 8)>>>(Wr2);

    // 1) gather span rows
    gather_kernel<<<NR, 256>>>(h, span);

    // 2) layer 1 (s & e batched): (512,1024)@(1024,2048), relu
    gemm_dual_kernel<true><<<dim3(D2 / BN, NR / BM, 2), 256>>>(
        gs, ge, Ws1, We1, bs1, be1, t1s, t1e, D2, D1, D2);

    // 3) layer 2 (s & e batched) + concat relu: (512,2048)@(2048,1024)
    gemm_dual_kernel<true><<<dim3(D1 / BN, NR / BM, 2), 256>>>(
        t1s, t1e, Ws2, We2, bs2, be2, cat, cat + D1, D1, D2, D2);

    // 4) entity_reps = cat @ Wo + bo: (512,2048)@(2048,2048)
    gemm_dual_kernel<false><<<dim3(D2 / BN, NR / BM, 1), 256>>>(
        cat, cat, Wo, Wo, bo, bo, ent, ent, D2, D2, D2);

    // 5) hi' = ent@Wr1a + br1 (bias folded), hj = ent@Wr1b
    gemm_dual_kernel<false><<<dim3(D2 / BN, NR / BM, 2), 256>>>(
        ent, ent, Wr1, Wr1 + (size_t)D2 * D2, br1, nullptr, hi, hj, D2, D2, D2);

    // 6) final fused GEMM on tensor cores (HMMA): M=32768, N=1024, K=2048
    final_mma_kernel<<<dim3(D1 / 128, (NB * NS * NS) / 128), 256, FINAL_SMEM>>>(
        br2, out);
}

// round 12
// speedup vs baseline: 1.5509x; 1.5509x over previous
#include <cuda_runtime.h>
#include <cuda_bf16.h>
#include <cstdint>

// Problem constants
#define NB 8          // batch
#define NL 512        // sequence length
#define NS 64         // spans per batch
#define NR 512        // NB*NS total span rows
#define D1 1024       // D
#define D2 2048       // 2*D

// ---------------------------------------------------------------------------
// Device scratch (no allocations allowed)
// ---------------------------------------------------------------------------
__device__ float g_gs [NR * D1];
__device__ float g_ge [NR * D1];
__device__ float g_t1s[NR * D2];
__device__ float g_t1e[NR * D2];
__device__ float g_cat[NR * D2];   // PRE-relu concat (relu applied at consumer)
__device__ float g_ent[NR * D2];
__device__ float g_hi [NR * D2];   // ent @ Wr1[:2048] + br1   (bias folded)
__device__ float g_hj [NR * D2];   // ent @ Wr1[2048:]
__device__ __nv_bfloat16 g_w2hi[D1 * D2];   // Wr2^T hi part  [n][k]
__device__ __nv_bfloat16 g_w2lo[D1 * D2];   // Wr2^T lo part  [n][k]

// ---------------------------------------------------------------------------
// PTX helpers (portable: sm_80-level features only)
// ---------------------------------------------------------------------------
static __device__ __forceinline__ uint32_t smem_u32(const void* p) {
    uint32_t a;
    asm("{ .reg .u64 t; cvta.to.shared.u64 t, %1; cvt.u32.u64 %0, t; }"
        : "=r"(a) : "l"(p));
    return a;
}

static __device__ __forceinline__ void cp16(uint32_t dst, const void* src) {
    asm volatile("cp.async.cg.shared.global [%0], [%1], 16;"
                 :: "r"(dst), "l"(src));
}
#define CP_COMMIT() asm volatile("cp.async.commit_group;" ::: "memory")
#define CP_WAIT(n)  asm volatile("cp.async.wait_group %0;" :: "n"(n) : "memory")

static __device__ __forceinline__ void ldsm4(uint32_t r[4], uint32_t addr) {
    asm volatile("ldmatrix.sync.aligned.m8n8.x4.shared.b16 {%0,%1,%2,%3}, [%4];"
                 : "=r"(r[0]), "=r"(r[1]), "=r"(r[2]), "=r"(r[3]) : "r"(addr));
}

static __device__ __forceinline__ void mma16816(float c[4], const uint32_t a[4],
                                                uint32_t b0, uint32_t b1) {
    asm volatile(
        "mma.sync.aligned.m16n8k16.row.col.f32.bf16.bf16.f32 "
        "{%0,%1,%2,%3}, {%4,%5,%6,%7}, {%8,%9}, {%0,%1,%2,%3};"
        : "+f"(c[0]), "+f"(c[1]), "+f"(c[2]), "+f"(c[3])
        : "r"(a[0]), "r"(a[1]), "r"(a[2]), "r"(a[3]), "r"(b0), "r"(b1));
}

static __device__ __forceinline__ uint32_t pack_bf16(__nv_bfloat16 a, __nv_bfloat16 b) {
    __nv_bfloat162 t = __halves2bfloat162(a, b);
    return *(uint32_t*)&t;
}

// ---------------------------------------------------------------------------
// Gather
// ---------------------------------------------------------------------------
__global__ void gather_kernel(const float* __restrict__ h,
                              const int* __restrict__ span)
{
    int bn = blockIdx.x;
    int b  = bn >> 6;
    int si = span[2 * bn + 0];
    int ei = span[2 * bn + 1];
    const float4* ps = (const float4*)(h + ((size_t)b * NL + (size_t)si) * D1);
    const float4* pe = (const float4*)(h + ((size_t)b * NL + (size_t)ei) * D1);
    float4* ds = (float4*)(g_gs + (size_t)bn * D1);
    float4* de = (float4*)(g_ge + (size_t)bn * D1);
    for (int t = threadIdx.x; t < D1 / 4; t += blockDim.x) {
        ds[t] = ps[t];
        de[t] = pe[t];
    }
}

// ---------------------------------------------------------------------------
// Prep: Wr2 (2048 x 1024, row-major) -> transposed bf16 hi/lo (1024 x 2048)
// ---------------------------------------------------------------------------
__global__ void prep_wr2_kernel(const float* __restrict__ W)
{
    __shared__ float tile[32][33];
    int n0 = blockIdx.x * 32;
    int k0 = blockIdx.y * 32;
    int tx = threadIdx.x, ty = threadIdx.y;
    for (int i = ty; i < 32; i += 8)
        tile[i][tx] = W[(size_t)(k0 + i) * D1 + n0 + tx];
    __syncthreads();
    for (int i = ty; i < 32; i += 8) {
        float v = tile[tx][i];               // = Wr2[k0+tx][n0+i]
        __nv_bfloat16 hv = __float2bfloat16_rn(v);
        float lof = v - __bfloat162float(hv);
        size_t o = (size_t)(n0 + i) * D2 + k0 + tx;
        g_w2hi[o] = hv;
        g_w2lo[o] = __float2bfloat16_rn(lof);
    }
}

// ---------------------------------------------------------------------------
// Generic fp32 SGEMM: C[M,N] = act(A'[M,K] @ W[K,N] + bias)
// A' = relu(A) when RELU_A. 128x128 tile, BK=8, same inner loop as R5 (proven).
// ZMODE: 0 = z is dual; 1 = z = split*2 + dual; 2 = z is split.
// SPLITK: each split covers K/2; results accumulated via atomicAdd
//         (C must be zeroed; bias added by split 0 only; no output relu).
// ---------------------------------------------------------------------------
#define BM 128
#define BN 128
#define BK 8
#define TM 8
#define TN 8

template<int ZMODE, bool RELU, bool RELU_A, bool SPLITK>
__global__ __launch_bounds__(256)
void gemm_dual_kernel(const float* __restrict__ A0, const float* __restrict__ A1,
                      const float* __restrict__ W0, const float* __restrict__ W1,
                      const float* __restrict__ bias0, const float* __restrict__ bias1,
                      float* __restrict__ C0, float* __restrict__ C1,
                      int N, int K, int ldc)
{
    int dual, sk;
    if (ZMODE == 0)      { dual = blockIdx.z;     sk = 0; }
    else if (ZMODE == 1) { dual = blockIdx.z & 1; sk = blockIdx.z >> 1; }
    else                 { dual = 0;              sk = blockIdx.z; }

    const float* A    = dual ? A1 : A0;
    const float* W    = dual ? W1 : W0;
    const float* bias = dual ? bias1 : bias0;
    float*       C    = dual ? C1 : C0;

    const int kLen = SPLITK ? (K >> 1) : K;
    const int kOff = sk * kLen;

    __shared__ float As[BK][BM];
    __shared__ float Bs[BK][BN];

    const int tid = threadIdx.x;
    const int tx  = tid & 15;
    const int ty  = tid >> 4;
    const int rowBase = blockIdx.y * BM;
    const int colBase = blockIdx.x * BN;

    const int l   = tid * 4;
    const int a_r = l >> 3;       // 0..127
    const int a_k = l & 7;        // 0 or 4
    const int b_k = l >> 7;       // 0..7
    const int b_c = l & 127;      // multiple of 4

    float acc[TM][TN];
#pragma unroll
    for (int i = 0; i < TM; i++)
#pragma unroll
        for (int j = 0; j < TN; j++) acc[i][j] = 0.f;

    const float* Aptr = A + (size_t)(rowBase + a_r) * K + kOff + a_k;
    const float* Wptr = W + (size_t)(kOff + b_k) * N + colBase + b_c;

    for (int k0 = 0; k0 < kLen; k0 += BK) {
        float4 av = *(const float4*)(Aptr + k0);
        if (RELU_A) {
            av.x = fmaxf(av.x, 0.f); av.y = fmaxf(av.y, 0.f);
            av.z = fmaxf(av.z, 0.f); av.w = fmaxf(av.w, 0.f);
        }
        As[a_k + 0][a_r] = av.x;
        As[a_k + 1][a_r] = av.y;
        As[a_k + 2][a_r] = av.z;
        As[a_k + 3][a_r] = av.w;
        *(float4*)&Bs[b_k][b_c] = *(const float4*)(Wptr + (size_t)k0 * N);
        __syncthreads();

#pragma unroll
        for (int kk = 0; kk < BK; kk++) {
            float4 a0 = *(const float4*)&As[kk][ty * TM];
            float4 a1 = *(const float4*)&As[kk][ty * TM + 4];
            float4 b0 = *(const float4*)&Bs[kk][tx * TN];
            float4 b1 = *(const float4*)&Bs[kk][tx * TN + 4];
            float a[TM] = {a0.x, a0.y, a0.z, a0.w, a1.x, a1.y, a1.z, a1.w};
            float bb[TN] = {b0.x, b0.y, b0.z, b0.w, b1.x, b1.y, b1.z, b1.w};
#pragma unroll
            for (int i = 0; i < TM; i++)
#pragma unroll
                for (int j = 0; j < TN; j++)
                    acc[i][j] = fmaf(a[i], bb[j], acc[i][j]);
        }
        __syncthreads();
    }

    float bj[TN];
#pragma unroll
    for (int j = 0; j < TN; j++) {
        bool addb = bias && (!SPLITK || sk == 0);
        bj[j] = addb ? bias[colBase + tx * TN + j] : 0.f;
    }

#pragma unroll
    for (int i = 0; i < TM; i++) {
        int r = rowBase + ty * TM + i;
        float* cp = C + (size_t)r * ldc + colBase + tx * TN;
#pragma unroll
        for (int j = 0; j < TN; j++) {
            float v = acc[i][j] + bj[j];
            if (SPLITK) {
                atomicAdd(cp + j, v);
            } else {
                if (RELU) v = fmaxf(v, 0.f);
                cp[j] = v;
            }
        }
    }
}

// ---------------------------------------------------------------------------
// Final GEMM on HMMA (mma.sync bf16, 3-term split, fp32 accum), 2-stage pipe
//   out[m,n] = relu(hi'[b,i,:] + hj[b,j,:]) @ Wr2 + br2     (br1 folded in hi')
//   m = ((b*64+i)*64+j), M=32768, K=2048, N=1024
// ---------------------------------------------------------------------------
#define KC   32
#define NC   (D2 / KC)        // 64 chunks
#define RSTR 80               // bytes per SMEM row (40 bf16, padded)
#define AHO  0
#define ALO_ 10240
#define BHO  20480
#define BLO_ 30720
#define STG  40960            // bytes per stage
#define FINAL_SMEM (2 * STG)  // 81920

__global__ __launch_bounds__(256)
void final_mma_kernel(const float* __restrict__ br2, float* __restrict__ out)
{
    extern __shared__ char smem[];
    const uint32_t sb = smem_u32(smem);
    const int tid  = threadIdx.x;
    const int lane = tid & 31;
    const int wid  = tid >> 5;
    const int wm   = wid >> 2;     // 0..1
    const int wn   = wid & 3;      // 0..3
    const int colBase = blockIdx.x * 128;
    const int rowBase = blockIdx.y * 128;

    const int fr = tid >> 1;
    const int fk = (tid & 1) << 4;
    const int m  = rowBase + fr;
    const int bI = m >> 12, iI = (m >> 6) & 63, jI = m & 63;
    const float* hiRow = g_hi + (size_t)((bI << 6) + iI) * D2;
    const float* hjRow = g_hj + (size_t)((bI << 6) + jI) * D2;
    const __nv_bfloat16* bhRow = g_w2hi + (size_t)(colBase + fr) * D2;
    const __nv_bfloat16* blRow = g_w2lo + (size_t)(colBase + fr) * D2;
    const uint32_t fillOff = (uint32_t)(fr * RSTR + fk * 2);

    float acc[4][4][4];
#pragma unroll
    for (int a = 0; a < 4; a++)
#pragma unroll
        for (int b = 0; b < 4; b++)
#pragma unroll
            for (int c = 0; c < 4; c++) acc[a][b][c] = 0.f;

    auto fill_stage = [&](int c) {
        const int st = (c & 1) * STG;
        const int k0 = c * KC;
        {
            uint32_t d = sb + BHO + st + fillOff;
            cp16(d,      bhRow + k0 + fk);
            cp16(d + 16, bhRow + k0 + fk + 8);
            d = sb + BLO_ + st + fillOff;
            cp16(d,      blRow + k0 + fk);
            cp16(d + 16, blRow + k0 + fk + 8);
        }
        const float4* xp = (const float4*)(hiRow + k0 + fk);
        const float4* yp = (const float4*)(hjRow + k0 + fk);
        uint32_t ah[8], al[8];
#pragma unroll
        for (int q = 0; q < 4; q++) {
            float4 x = xp[q], y = yp[q];
            float v0 = fmaxf(x.x + y.x, 0.f);
            float v1 = fmaxf(x.y + y.y, 0.f);
            float v2 = fmaxf(x.z + y.z, 0.f);
            float v3 = fmaxf(x.w + y.w, 0.f);
            __nv_bfloat16 h0 = __float2bfloat16_rn(v0);
            __nv_bfloat16 h1 = __float2bfloat16_rn(v1);
            __nv_bfloat16 h2 = __float2bfloat16_rn(v2);
            __nv_bfloat16 h3 = __float2bfloat16_rn(v3);
            ah[2 * q + 0] = pack_bf16(h0, h1);
            ah[2 * q + 1] = pack_bf16(h2, h3);
            al[2 * q + 0] = pack_bf16(__float2bfloat16_rn(v0 - __bfloat162float(h0)),
                                      __float2bfloat16_rn(v1 - __bfloat162float(h1)));
            al[2 * q + 1] = pack_bf16(__float2bfloat16_rn(v2 - __bfloat162float(h2)),
                                      __float2bfloat16_rn(v3 - __bfloat162float(h3)));
        }
        char* da = smem + AHO + st + fillOff;
        *(uint4*)(da)      = make_uint4(ah[0], ah[1], ah[2], ah[3]);
        *(uint4*)(da + 16) = make_uint4(ah[4], ah[5], ah[6], ah[7]);
        char* dl = smem + ALO_ + st + fillOff;
        *(uint4*)(dl)      = make_uint4(al[0], al[1], al[2], al[3]);
        *(uint4*)(dl + 16) = make_uint4(al[4], al[5], al[6], al[7]);
    };

    const uint32_t aOff = (uint32_t)((wm * 64 + (lane & 15)) * RSTR + ((lane >> 4) * 8) * 2);
    const uint32_t bOff = (uint32_t)((wn * 32 + (lane & 7) + ((lane >> 4) & 1) * 8) * RSTR
                                     + (((lane >> 3) & 1) * 8) * 2);

    // ---- prologue ----
    fill_stage(0);
    CP_COMMIT();

    for (int c = 0; c < NC; c++) {
        if (c + 1 < NC) {
            fill_stage(c + 1);
            CP_COMMIT();
            CP_WAIT(1);
        } else {
            CP_WAIT(0);
        }
        __syncthreads();   // stage c fully visible

        const int st = (c & 1) * STG;
        const uint32_t aH = sb + AHO + st + aOff;
        const uint32_t aL = sb + ALO_ + st + aOff;
        const uint32_t bH = sb + BHO + st + bOff;
        const uint32_t bL = sb + BLO_ + st + bOff;

#pragma unroll
        for (int ks = 0; ks < KC; ks += 16) {
            uint32_t ah[4][4], al4[4][4], bh[2][4], bl[2][4];
#pragma unroll
            for (int mt = 0; mt < 4; mt++) {
                ldsm4(ah[mt],  aH + mt * (16 * RSTR) + ks * 2);
                ldsm4(al4[mt], aL + mt * (16 * RSTR) + ks * 2);
            }
#pragma unroll
            for (int np = 0; np < 2; np++) {
                ldsm4(bh[np], bH + np * (16 * RSTR) + ks * 2);
                ldsm4(bl[np], bL + np * (16 * RSTR) + ks * 2);
            }
#pragma unroll
            for (int mt = 0; mt < 4; mt++) {
#pragma unroll
                for (int nt = 0; nt < 4; nt++) {
                    const int np = nt >> 1, h = (nt & 1) * 2;
                    mma16816(acc[mt][nt], ah[mt],  bh[np][h], bh[np][h + 1]);
                    mma16816(acc[mt][nt], ah[mt],  bl[np][h], bl[np][h + 1]);
                    mma16816(acc[mt][nt], al4[mt], bh[np][h], bh[np][h + 1]);
                }
            }
        }
        __syncthreads();   // readers done before refill of this stage
    }

    // ---- epilogue: acc -> out (+br2) ----
#pragma unroll
    for (int mt = 0; mt < 4; mt++) {
        const int r0 = rowBase + wm * 64 + mt * 16 + (lane >> 2);
#pragma unroll
        for (int nt = 0; nt < 4; nt++) {
            const int col = colBase + wn * 32 + nt * 8 + (lane & 3) * 2;
            const float b0 = br2[col], b1 = br2[col + 1];
            float2 v01 = make_float2(acc[mt][nt][0] + b0, acc[mt][nt][1] + b1);
            float2 v23 = make_float2(acc[mt][nt][2] + b0, acc[mt][nt][3] + b1);
            *(float2*)(out + (size_t)r0 * D1 + col)       = v01;
            *(float2*)(out + (size_t)(r0 + 8) * D1 + col) = v23;
        }
    }
}

// ---------------------------------------------------------------------------
// Launcher
// ---------------------------------------------------------------------------
extern "C" void kernel_launch(void* const* d_in, const int* in_sizes, int n_in,
                              void* d_out, int out_size)
{
    const float* h    = (const float*)d_in[0];
    const int*   span = (const int*)d_in[1];
    const float* Ws1 = (const float*)d_in[2];
    const float* bs1 = (const float*)d_in[3];
    const float* Ws2 = (const float*)d_in[4];
    const float* bs2 = (const float*)d_in[5];
    const float* We1 = (const float*)d_in[6];
    const float* be1 = (const float*)d_in[7];
    const float* We2 = (const float*)d_in[8];
    const float* be2 = (const float*)d_in[9];
    const float* Wo  = (const float*)d_in[10];
    const float* bo  = (const float*)d_in[11];
    const float* Wr1 = (const float*)d_in[12];
    const float* br1 = (const float*)d_in[13];
    const float* Wr2 = (const float*)d_in[14];
    const float* br2 = (const float*)d_in[15];
    float* out = (float*)d_out;

    float *gs, *ge, *t1s, *t1e, *cat, *ent, *hi, *hj;
    cudaGetSymbolAddress((void**)&gs,  g_gs);
    cudaGetSymbolAddress((void**)&ge,  g_ge);
    cudaGetSymbolAddress((void**)&t1s, g_t1s);
    cudaGetSymbolAddress((void**)&t1e, g_t1e);
    cudaGetSymbolAddress((void**)&cat, g_cat);
    cudaGetSymbolAddress((void**)&ent, g_ent);
    cudaGetSymbolAddress((void**)&hi,  g_hi);
    cudaGetSymbolAddress((void**)&hj,  g_hj);

    cudaFuncSetAttribute(final_mma_kernel,
                         cudaFuncAttributeMaxDynamicSharedMemorySize, FINAL_SMEM);

    // zero split-K accumulation targets (graph-capturable async memsets)
    cudaMemsetAsync(cat, 0, (size_t)NR * D2 * sizeof(float));
    cudaMemsetAsync(ent, 0, (size_t)NR * D2 * sizeof(float));

    // 0) prep: transpose + bf16-split Wr2 (independent)
    prep_wr2_kernel<<<dim3(D1 / 32, D2 / 32), dim3(32, 8)>>>(Wr2);

    // 1) gather span rows
    gather_kernel<<<NR, 256>>>(h, span);

    // 2) layer 1 (s & e batched): (512,1024)@(1024,2048), relu out
    gemm_dual_kernel<0, true, false, false><<<dim3(D2 / BN, NR / BM, 2), 256>>>(
        gs, ge, Ws1, We1, bs1, be1, t1s, t1e, D2, D1, D2);

    // 3) layer 2 (s & e) SPLIT-K=2: (512,2048)@(2048,1024) -> cat (pre-relu)
    //    z = split*2 + dual  -> grid.z = 4 (128 CTAs total)
    gemm_dual_kernel<1, false, false, true><<<dim3(D1 / BN, NR / BM, 4), 256>>>(
        t1s, t1e, Ws2, We2, bs2, be2, cat, cat + D1, D1, D2, D2);

    // 4) entity_reps = relu(cat) @ Wo + bo, SPLIT-K=2: (512,2048)@(2048,2048)
    //    relu applied at A-load; z = split -> grid.z = 2 (128 CTAs total)
    gemm_dual_kernel<2, false, true, true><<<dim3(D2 / BN, NR / BM, 2), 256>>>(
        cat, cat, Wo, Wo, bo, bo, ent, ent, D2, D2, D2);

    // 5) hi' = ent@Wr1a + br1 (bias folded), hj = ent@Wr1b
    gemm_dual_kernel<0, false, false, false><<<dim3(D2 / BN, NR / BM, 2), 256>>>(
        ent, ent, Wr1, Wr1 + (size_t)D2 * D2, br1, nullptr, hi, hj, D2, D2, D2);

    // 6) final fused GEMM on tensor cores (HMMA): M=32768, N=1024, K=2048
    final_mma_kernel<<<dim3(D1 / 128, (NB * NS * NS) / 128), 256, FINAL_SMEM>>>(
        br2, out);
}

// round 14
// speedup vs baseline: 1.5757x; 1.0160x over previous
#include <cuda_runtime.h>
#include <cuda_bf16.h>
#include <cstdint>

// Problem constants
#define NB 8          // batch
#define NL 512        // sequence length
#define NS 64         // spans per batch
#define NR 512        // NB*NS total span rows
#define D1 1024       // D
#define D2 2048       // 2*D
#define MF (NB * NS * NS)   // 32768 final rows

typedef __nv_bfloat16 bf16;

// ---------------------------------------------------------------------------
// Device scratch (no allocations allowed)
// ---------------------------------------------------------------------------
__device__ float g_gs [NR * D1];
__device__ float g_ge [NR * D1];
__device__ float g_t1s[NR * D2];
__device__ float g_t1e[NR * D2];
__device__ float g_cat[NR * D2];   // PRE-relu concat (relu applied at consumer)
__device__ float g_ent[NR * D2];
__device__ float g_hi [NR * D2];   // ent @ Wr1[:2048] + br1   (bias folded)
__device__ float g_hj [NR * D2];   // ent @ Wr1[2048:]
__device__ bf16 g_w2hi[D1 * D2];   // Wr2^T hi part  [n][k]
__device__ bf16 g_w2lo[D1 * D2];   // Wr2^T lo part  [n][k]
__device__ bf16 g_ah[(size_t)MF * D2];   // relu(hi'+hj) hi split [m][k]
__device__ bf16 g_al[(size_t)MF * D2];   // relu(hi'+hj) lo split [m][k]

// ---------------------------------------------------------------------------
// PTX helpers (portable: sm_80-level features only)
// ---------------------------------------------------------------------------
static __device__ __forceinline__ uint32_t smem_u32(const void* p) {
    uint32_t a;
    asm("{ .reg .u64 t; cvta.to.shared.u64 t, %1; cvt.u32.u64 %0, t; }"
        : "=r"(a) : "l"(p));
    return a;
}

static __device__ __forceinline__ void cp16(uint32_t dst, const void* src) {
    asm volatile("cp.async.cg.shared.global [%0], [%1], 16;"
                 :: "r"(dst), "l"(src));
}
#define CP_COMMIT() asm volatile("cp.async.commit_group;" ::: "memory")
#define CP_WAIT(n)  asm volatile("cp.async.wait_group %0;" :: "n"(n) : "memory")

static __device__ __forceinline__ void ldsm4(uint32_t r[4], uint32_t addr) {
    asm volatile("ldmatrix.sync.aligned.m8n8.x4.shared.b16 {%0,%1,%2,%3}, [%4];"
                 : "=r"(r[0]), "=r"(r[1]), "=r"(r[2]), "=r"(r[3]) : "r"(addr));
}

static __device__ __forceinline__ void mma16816(float c[4], const uint32_t a[4],
                                                uint32_t b0, uint32_t b1) {
    asm volatile(
        "mma.sync.aligned.m16n8k16.row.col.f32.bf16.bf16.f32 "
        "{%0,%1,%2,%3}, {%4,%5,%6,%7}, {%8,%9}, {%0,%1,%2,%3};"
        : "+f"(c[0]), "+f"(c[1]), "+f"(c[2]), "+f"(c[3])
        : "r"(a[0]), "r"(a[1]), "r"(a[2]), "r"(a[3]), "r"(b0), "r"(b1));
}

static __device__ __forceinline__ uint32_t pack_bf16(bf16 a, bf16 b) {
    __nv_bfloat162 t = __halves2bfloat162(a, b);
    return *(uint32_t*)&t;
}

// ---------------------------------------------------------------------------
// Gather
// ---------------------------------------------------------------------------
__global__ void gather_kernel(const float* __restrict__ h,
                              const int* __restrict__ span)
{
    int bn = blockIdx.x;
    int b  = bn >> 6;
    int si = span[2 * bn + 0];
    int ei = span[2 * bn + 1];
    const float4* ps = (const float4*)(h + ((size_t)b * NL + (size_t)si) * D1);
    const float4* pe = (const float4*)(h + ((size_t)b * NL + (size_t)ei) * D1);
    float4* ds = (float4*)(g_gs + (size_t)bn * D1);
    float4* de = (float4*)(g_ge + (size_t)bn * D1);
    for (int t = threadIdx.x; t < D1 / 4; t += blockDim.x) {
        ds[t] = ps[t];
        de[t] = pe[t];
    }
}

// ---------------------------------------------------------------------------
// Prep: Wr2 (2048 x 1024, row-major) -> transposed bf16 hi/lo (1024 x 2048)
// ---------------------------------------------------------------------------
__global__ void prep_wr2_kernel(const float* __restrict__ W)
{
    __shared__ float tile[32][33];
    int n0 = blockIdx.x * 32;
    int k0 = blockIdx.y * 32;
    int tx = threadIdx.x, ty = threadIdx.y;
    for (int i = ty; i < 32; i += 8)
        tile[i][tx] = W[(size_t)(k0 + i) * D1 + n0 + tx];
    __syncthreads();
    for (int i = ty; i < 32; i += 8) {
        float v = tile[tx][i];               // = Wr2[k0+tx][n0+i]
        bf16 hv = __float2bfloat16_rn(v);
        float lof = v - __bfloat162float(hv);
        size_t o = (size_t)(n0 + i) * D2 + k0 + tx;
        g_w2hi[o] = hv;
        g_w2lo[o] = __float2bfloat16_rn(lof);
    }
}

// ---------------------------------------------------------------------------
// Prep hidden: A[m][k] = relu(hi'[(b,i)][k] + hj[(b,j)][k]) -> bf16 hi/lo
// m = ((b*64+i)*64+j). One block per m row; hi/hj rows are L2-resident.
// ---------------------------------------------------------------------------
__global__ __launch_bounds__(256)
void prep_hidden_kernel()
{
    const int m  = blockIdx.x;
    const int bI = m >> 12, iI = (m >> 6) & 63, jI = m & 63;
    const float4* hp = (const float4*)(g_hi + (size_t)((bI << 6) + iI) * D2);
    const float4* jp = (const float4*)(g_hj + (size_t)((bI << 6) + jI) * D2);
    bf16* oh = g_ah + (size_t)m * D2;
    bf16* ol = g_al + (size_t)m * D2;

    const int t = threadIdx.x;           // 256 threads x 8 elems
#pragma unroll
    for (int q = 0; q < 2; q++) {
        const int e4 = t * 2 + q;        // float4 index 0..511
        float4 x = hp[e4], y = jp[e4];
        float v0 = fmaxf(x.x + y.x, 0.f);
        float v1 = fmaxf(x.y + y.y, 0.f);
        float v2 = fmaxf(x.z + y.z, 0.f);
        float v3 = fmaxf(x.w + y.w, 0.f);
        bf16 h0 = __float2bfloat16_rn(v0);
        bf16 h1 = __float2bfloat16_rn(v1);
        bf16 h2 = __float2bfloat16_rn(v2);
        bf16 h3 = __float2bfloat16_rn(v3);
        *(uint2*)(oh + e4 * 4) = make_uint2(pack_bf16(h0, h1), pack_bf16(h2, h3));
        *(uint2*)(ol + e4 * 4) = make_uint2(
            pack_bf16(__float2bfloat16_rn(v0 - __bfloat162float(h0)),
                      __float2bfloat16_rn(v1 - __bfloat162float(h1))),
            pack_bf16(__float2bfloat16_rn(v2 - __bfloat162float(h2)),
                      __float2bfloat16_rn(v3 - __bfloat162float(h3))));
    }
}

// ---------------------------------------------------------------------------
// Generic fp32 SGEMM: C[M,N] = act(A'[M,K] @ W[K,N] + bias)
// A' = relu(A) when RELU_A. 128x128 tile, BK=8 (proven R5 inner loop).
// ZMODE: 0 = z is dual; 1 = z = split*2 + dual; 2 = z is split.
// SPLITK: each split covers K/2; accumulate via atomicAdd (C pre-zeroed,
//         bias added by split 0 only; no output relu).
// ---------------------------------------------------------------------------
#define BM 128
#define BN 128
#define BK 8
#define TM 8
#define TN 8

template<int ZMODE, bool RELU, bool RELU_A, bool SPLITK>
__global__ __launch_bounds__(256)
void gemm_dual_kernel(const float* __restrict__ A0, const float* __restrict__ A1,
                      const float* __restrict__ W0, const float* __restrict__ W1,
                      const float* __restrict__ bias0, const float* __restrict__ bias1,
                      float* __restrict__ C0, float* __restrict__ C1,
                      int N, int K, int ldc)
{
    int dual, sk;
    if (ZMODE == 0)      { dual = blockIdx.z;     sk = 0; }
    else if (ZMODE == 1) { dual = blockIdx.z & 1; sk = blockIdx.z >> 1; }
    else                 { dual = 0;              sk = blockIdx.z; }

    const float* A    = dual ? A1 : A0;
    const float* W    = dual ? W1 : W0;
    const float* bias = dual ? bias1 : bias0;
    float*       C    = dual ? C1 : C0;

    const int kLen = SPLITK ? (K >> 1) : K;
    const int kOff = sk * kLen;

    __shared__ float As[BK][BM];
    __shared__ float Bs[BK][BN];

    const int tid = threadIdx.x;
    const int tx  = tid & 15;
    const int ty  = tid >> 4;
    const int rowBase = blockIdx.y * BM;
    const int colBase = blockIdx.x * BN;

    const int l   = tid * 4;
    const int a_r = l >> 3;       // 0..127
    const int a_k = l & 7;        // 0 or 4
    const int b_k = l >> 7;       // 0..7
    const int b_c = l & 127;      // multiple of 4

    float acc[TM][TN];
#pragma unroll
    for (int i = 0; i < TM; i++)
#pragma unroll
        for (int j = 0; j < TN; j++) acc[i][j] = 0.f;

    const float* Aptr = A + (size_t)(rowBase + a_r) * K + kOff + a_k;
    const float* Wptr = W + (size_t)(kOff + b_k) * N + colBase + b_c;

    for (int k0 = 0; k0 < kLen; k0 += BK) {
        float4 av = *(const float4*)(Aptr + k0);
        if (RELU_A) {
            av.x = fmaxf(av.x, 0.f); av.y = fmaxf(av.y, 0.f);
            av.z = fmaxf(av.z, 0.f); av.w = fmaxf(av.w, 0.f);
        }
        As[a_k + 0][a_r] = av.x;
        As[a_k + 1][a_r] = av.y;
        As[a_k + 2][a_r] = av.z;
        As[a_k + 3][a_r] = av.w;
        *(float4*)&Bs[b_k][b_c] = *(const float4*)(Wptr + (size_t)k0 * N);
        __syncthreads();

#pragma unroll
        for (int kk = 0; kk < BK; kk++) {
            float4 a0 = *(const float4*)&As[kk][ty * TM];
            float4 a1 = *(const float4*)&As[kk][ty * TM + 4];
            float4 b0 = *(const float4*)&Bs[kk][tx * TN];
            float4 b1 = *(const float4*)&Bs[kk][tx * TN + 4];
            float a[TM] = {a0.x, a0.y, a0.z, a0.w, a1.x, a1.y, a1.z, a1.w};
            float bb[TN] = {b0.x, b0.y, b0.z, b0.w, b1.x, b1.y, b1.z, b1.w};
#pragma unroll
            for (int i = 0; i < TM; i++)
#pragma unroll
                for (int j = 0; j < TN; j++)
                    acc[i][j] = fmaf(a[i], bb[j], acc[i][j]);
        }
        __syncthreads();
    }

    float bj[TN];
#pragma unroll
    for (int j = 0; j < TN; j++) {
        bool addb = bias && (!SPLITK || sk == 0);
        bj[j] = addb ? bias[colBase + tx * TN + j] : 0.f;
    }

#pragma unroll
    for (int i = 0; i < TM; i++) {
        int r = rowBase + ty * TM + i;
        float* cp = C + (size_t)r * ldc + colBase + tx * TN;
#pragma unroll
        for (int j = 0; j < TN; j++) {
            float v = acc[i][j] + bj[j];
            if (SPLITK) {
                atomicAdd(cp + j, v);
            } else {
                if (RELU) v = fmaxf(v, 0.f);
                cp[j] = v;
            }
        }
    }
}

// ---------------------------------------------------------------------------
// Final GEMM on HMMA (mma.sync bf16, 3-term split, fp32 accum), 2-stage pipe.
// A and B both precomputed bf16 splits -> pure cp.async fill.
//   out[m,n] = A[m,:] (3-term) W2^T[n,:] + br2
// ---------------------------------------------------------------------------
#define KC   32
#define NC   (D2 / KC)        // 64 chunks
#define RSTR 80               // bytes per SMEM row (40 bf16, padded)
#define AHO  0
#define ALO_ 10240
#define BHO  20480
#define BLO_ 30720
#define STG  40960            // bytes per stage
#define FINAL_SMEM (2 * STG)  // 81920

__global__ __launch_bounds__(256)
void final_mma_kernel(const float* __restrict__ br2, float* __restrict__ out)
{
    extern __shared__ char smem[];
    const uint32_t sb = smem_u32(smem);
    const int tid  = threadIdx.x;
    const int lane = tid & 31;
    const int wid  = tid >> 5;
    const int wm   = wid >> 2;     // 0..1
    const int wn   = wid & 3;      // 0..3
    const int colBase = blockIdx.x * 128;
    const int rowBase = blockIdx.y * 128;

    const int fr = tid >> 1;
    const int fk = (tid & 1) << 4;
    const bf16* ahRow = g_ah + (size_t)(rowBase + fr) * D2;
    const bf16* alRow = g_al + (size_t)(rowBase + fr) * D2;
    const bf16* bhRow = g_w2hi + (size_t)(colBase + fr) * D2;
    const bf16* blRow = g_w2lo + (size_t)(colBase + fr) * D2;
    const uint32_t fillOff = (uint32_t)(fr * RSTR + fk * 2);

    float acc[4][4][4];
#pragma unroll
    for (int a = 0; a < 4; a++)
#pragma unroll
        for (int b = 0; b < 4; b++)
#pragma unroll
            for (int c = 0; c < 4; c++) acc[a][b][c] = 0.f;

    auto fill_stage = [&](int c) {
        const int st = (c & 1) * STG;
        const int k0 = c * KC;
        uint32_t d = sb + AHO + st + fillOff;
        cp16(d,      ahRow + k0 + fk);
        cp16(d + 16, ahRow + k0 + fk + 8);
        d = sb + ALO_ + st + fillOff;
        cp16(d,      alRow + k0 + fk);
        cp16(d + 16, alRow + k0 + fk + 8);
        d = sb + BHO + st + fillOff;
        cp16(d,      bhRow + k0 + fk);
        cp16(d + 16, bhRow + k0 + fk + 8);
        d = sb + BLO_ + st + fillOff;
        cp16(d,      blRow + k0 + fk);
        cp16(d + 16, blRow + k0 + fk + 8);
    };

    const uint32_t aOff = (uint32_t)((wm * 64 + (lane & 15)) * RSTR + ((lane >> 4) * 8) * 2);
    const uint32_t bOff = (uint32_t)((wn * 32 + (lane & 7) + ((lane >> 4) & 1) * 8) * RSTR
                                     + (((lane >> 3) & 1) * 8) * 2);

    // ---- prologue ----
    fill_stage(0);
    CP_COMMIT();

    for (int c = 0; c < NC; c++) {
        if (c + 1 < NC) {
            fill_stage(c + 1);
            CP_COMMIT();
            CP_WAIT(1);
        } else {
            CP_WAIT(0);
        }
        __syncthreads();   // stage c fully visible

        const int st = (c & 1) * STG;
        const uint32_t aH = sb + AHO + st + aOff;
        const uint32_t aL = sb + ALO_ + st + aOff;
        const uint32_t bH = sb + BHO + st + bOff;
        const uint32_t bL = sb + BLO_ + st + bOff;

#pragma unroll
        for (int ks = 0; ks < KC; ks += 16) {
            uint32_t ah[4][4], al4[4][4], bh[2][4], bl[2][4];
#pragma unroll
            for (int mt = 0; mt < 4; mt++) {
                ldsm4(ah[mt],  aH + mt * (16 * RSTR) + ks * 2);
                ldsm4(al4[mt], aL + mt * (16 * RSTR) + ks * 2);
            }
#pragma unroll
            for (int np = 0; np < 2; np++) {
                ldsm4(bh[np], bH + np * (16 * RSTR) + ks * 2);
                ldsm4(bl[np], bL + np * (16 * RSTR) + ks * 2);
            }
#pragma unroll
            for (int mt = 0; mt < 4; mt++) {
#pragma unroll
                for (int nt = 0; nt < 4; nt++) {
                    const int np = nt >> 1, h = (nt & 1) * 2;
                    mma16816(acc[mt][nt], ah[mt],  bh[np][h], bh[np][h + 1]);
                    mma16816(acc[mt][nt], ah[mt],  bl[np][h], bl[np][h + 1]);
                    mma16816(acc[mt][nt], al4[mt], bh[np][h], bh[np][h + 1]);
                }
            }
        }
        __syncthreads();   // readers done before refill of this stage
    }

    // ---- epilogue: acc -> out (+br2) ----
#pragma unroll
    for (int mt = 0; mt < 4; mt++) {
        const int r0 = rowBase + wm * 64 + mt * 16 + (lane >> 2);
#pragma unroll
        for (int nt = 0; nt < 4; nt++) {
            const int col = colBase + wn * 32 + nt * 8 + (lane & 3) * 2;
            const float b0 = br2[col], b1 = br2[col + 1];
            float2 v01 = make_float2(acc[mt][nt][0] + b0, acc[mt][nt][1] + b1);
            float2 v23 = make_float2(acc[mt][nt][2] + b0, acc[mt][nt][3] + b1);
            *(float2*)(out + (size_t)r0 * D1 + col)       = v01;
            *(float2*)(out + (size_t)(r0 + 8) * D1 + col) = v23;
        }
    }
}

// ---------------------------------------------------------------------------
// Launcher
// ---------------------------------------------------------------------------
extern "C" void kernel_launch(void* const* d_in, const int* in_sizes, int n_in,
                              void* d_out, int out_size)
{
    const float* h    = (const float*)d_in[0];
    const int*   span = (const int*)d_in[1];
    const float* Ws1 = (const float*)d_in[2];
    const float* bs1 = (const float*)d_in[3];
    const float* Ws2 = (const float*)d_in[4];
    const float* bs2 = (const float*)d_in[5];
    const float* We1 = (const float*)d_in[6];
    const float* be1 = (const float*)d_in[7];
    const float* We2 = (const float*)d_in[8];
    const float* be2 = (const float*)d_in[9];
    const float* Wo  = (const float*)d_in[10];
    const float* bo  = (const float*)d_in[11];
    const float* Wr1 = (const float*)d_in[12];
    const float* br1 = (const float*)d_in[13];
    const float* Wr2 = (const float*)d_in[14];
    const float* br2 = (const float*)d_in[15];
    float* out = (float*)d_out;

    float *gs, *ge, *t1s, *t1e, *cat, *ent, *hi, *hj;
    cudaGetSymbolAddress((void**)&gs,  g_gs);
    cudaGetSymbolAddress((void**)&ge,  g_ge);
    cudaGetSymbolAddress((void**)&t1s, g_t1s);
    cudaGetSymbolAddress((void**)&t1e, g_t1e);
    cudaGetSymbolAddress((void**)&cat, g_cat);
    cudaGetSymbolAddress((void**)&ent, g_ent);
    cudaGetSymbolAddress((void**)&hi,  g_hi);
    cudaGetSymbolAddress((void**)&hj,  g_hj);

    cudaFuncSetAttribute(final_mma_kernel,
                         cudaFuncAttributeMaxDynamicSharedMemorySize, FINAL_SMEM);

    // zero split-K accumulation targets (graph-capturable async memsets)
    cudaMemsetAsync(cat, 0, (size_t)NR * D2 * sizeof(float));
    cudaMemsetAsync(ent, 0, (size_t)NR * D2 * sizeof(float));

    // 0) prep: transpose + bf16-split Wr2 (independent)
    prep_wr2_kernel<<<dim3(D1 / 32, D2 / 32), dim3(32, 8)>>>(Wr2);

    // 1) gather span rows
    gather_kernel<<<NR, 256>>>(h, span);

    // 2) layer 1 (s & e batched): (512,1024)@(1024,2048), relu out
    gemm_dual_kernel<0, true, false, false><<<dim3(D2 / BN, NR / BM, 2), 256>>>(
        gs, ge, Ws1, We1, bs1, be1, t1s, t1e, D2, D1, D2);

    // 3) layer 2 (s & e) SPLIT-K=2: (512,2048)@(2048,1024) -> cat (pre-relu)
    gemm_dual_kernel<1, false, false, true><<<dim3(D1 / BN, NR / BM, 4), 256>>>(
        t1s, t1e, Ws2, We2, bs2, be2, cat, cat + D1, D1, D2, D2);

    // 4) entity_reps = relu(cat) @ Wo + bo, SPLIT-K=2: (512,2048)@(2048,2048)
    gemm_dual_kernel<2, false, true, true><<<dim3(D2 / BN, NR / BM, 2), 256>>>(
        cat, cat, Wo, Wo, bo, bo, ent, ent, D2, D2, D2);

    // 5) hi' = ent@Wr1a + br1 (bias folded), hj = ent@Wr1b
    gemm_dual_kernel<0, false, false, false><<<dim3(D2 / BN, NR / BM, 2), 256>>>(
        ent, ent, Wr1, Wr1 + (size_t)D2 * D2, br1, nullptr, hi, hj, D2, D2, D2);

    // 5b) materialize bf16 split of relu(hi'+hj) once (removes x8 redundant
    //     conversion work from the final kernel's A fill)
    prep_hidden_kernel<<<MF, 256>>>();

    // 6) final fused GEMM on tensor cores (HMMA): M=32768, N=1024, K=2048
    final_mma_kernel<<<dim3(D1 / 128, MF / 128), 256, FINAL_SMEM>>>(
        br2, out);
}